// round 13
// baseline (speedup 1.0000x reference)
#include <cuda_runtime.h>
#include <cstdint>

// out[b,k,oc,x] = sum_ci W[k,oc,ci]*in[b,ci,k,x] + bias[k,oc]
// in: [4096,128,9,9]  w: [9,128,128]  bias: [9,128]  out: [4096,9,128,9] (f32)
//
// R13: CTA tile M=128 x N=144 (16 batches), 12 warps = 4(M) x 3(N).
// Warp tile 32oc x 48n: 2 m-frags x 6 n-frags -> 12 HMMA per kstep,
// A-LDG/HMMA = 0.67 wavefronts (halved), syncs per HMMA halved.
// A-frags packed (tf32-rna) in g_W2; X via cp.async raw f32 (tf32 trunc),
// 4 quarter-K stages (32 ci x 144 n), wait_group 2, sync per quarter.

#define KK     9
#define CIN    128
#define COUT   128
#define NB     16
#define TILES  4
#define NTHR   384
#define NBUF   4
#define NSTEP  (NBUF * TILES)   // 16 quarters per CTA

#define SXS 152                 // stage row stride: 152%32=24 -> B-frag banks (24tl+g) perfect
#define XQ_WORDS (32 * SXS)     // 4864 words per quarter (19456 B)
#define SMEM_BYTES (NBUF * XQ_WORDS * 4)   // 77824 -> 2 CTAs/SM

// packed A-frags: [k][wm(4)][ks(16)][mf(2)][lane(32)][4] tf32 bits
#define W2_WORDS (KK * 4 * 16 * 2 * 32 * 4)   // 147456
__device__ uint32_t g_W2[W2_WORDS];

__device__ __forceinline__ uint32_t f2tf32(float f) {
    uint32_t u;
    asm("cvt.rna.tf32.f32 %0, %1;" : "=r"(u) : "f"(f));
    return u;
}
__device__ __forceinline__ uint32_t smem_u32(const void* p) {
    uint32_t a;
    asm("{ .reg .u64 t; cvta.to.shared.u64 t, %1; cvt.u32.u64 %0, t; }" : "=r"(a) : "l"(p));
    return a;
}
__device__ __forceinline__ void cp4(uint32_t dst, const float* src) {
    asm volatile("cp.async.ca.shared.global [%0], [%1], 4;" :: "r"(dst), "l"(src));
}
__device__ __forceinline__ void mma_tf32(float* d, const uint32_t* a, const uint32_t* b) {
    asm volatile(
        "mma.sync.aligned.m16n8k8.row.col.f32.tf32.tf32.f32 "
        "{%0,%1,%2,%3}, {%4,%5,%6,%7}, {%8,%9}, {%0,%1,%2,%3};"
        : "+f"(d[0]), "+f"(d[1]), "+f"(d[2]), "+f"(d[3])
        : "r"(a[0]), "r"(a[1]), "r"(a[2]), "r"(a[3]), "r"(b[0]), "r"(b[1]));
}

// ---- prep: w[9][128][128] f32 -> g_W2 packed tf32 A-frags ----
__global__ void prep_w_kernel(const float* __restrict__ w) {
    int idx = blockIdx.x * 256 + threadIdx.x;      // 0..147455
    if (idx >= W2_WORDS) return;
    int j    = idx & 3;
    int lane = (idx >> 2) & 31;
    int mf   = (idx >> 7) & 1;
    int ks   = (idx >> 8) & 15;
    int wm   = (idx >> 12) & 3;
    int k    = idx >> 14;
    int g = lane >> 2, tl = lane & 3;
    int oc = wm * 32 + mf * 16 + g + (j & 1) * 8;
    int ci = ks * 8 + tl + ((j >> 1) & 1) * 4;
    g_W2[idx] = f2tf32(w[(k * COUT + oc) * CIN + ci]);
}

__global__ void __launch_bounds__(NTHR, 2)
gather_vertical_r13(const float* __restrict__ in,
                    const float* __restrict__ bias,
                    float* __restrict__ out)
{
    extern __shared__ uint32_t sX[];               // 4 stages [32 ci][144 n] stride SXS

    const int tid = threadIdx.x;
    const int k   = blockIdx.x;
    const int yid = blockIdx.y;
    const int bbase = yid * TILES * NB;

    // ---- cp.async mapping: row-based. 512 rows (16 bl x 32 ci) of 9 words.
    //      thread handles row tid, plus row tid+384 if tid<128. ----
    const float* src = in + (size_t)bbase * (CIN * 81) + (size_t)k * 9;
    const uint32_t sx_base = smem_u32(sX);
    const int r1  = tid;                 // 0..383
    const int bl1 = r1 >> 5, ci1 = r1 & 31;
    const int g1  = (bl1 * CIN + ci1) * 81;
    const uint32_t s1 = (ci1 * SXS + bl1 * 9) * 4;
    const int r2  = tid + 384;           // 384..511 (valid if tid<128)
    const int bl2 = r2 >> 5, ci2 = r2 & 31;
    const int g2  = (bl2 * CIN + ci2) * 81;
    const uint32_t s2 = (ci2 * SXS + bl2 * 9) * 4;
    const bool two = (tid < 128);

    // ---- prologue: stages 0..2 (tile 0, quarters 0..2) ----
    #pragma unroll
    for (int s = 0; s < 3; s++) {
        const float* st = src + s * 32 * 81;
        const uint32_t db = sx_base + s * (XQ_WORDS * 4);
        #pragma unroll
        for (int x = 0; x < 9; x++) cp4(db + s1 + 4 * x, st + g1 + x);
        if (two) {
            #pragma unroll
            for (int x = 0; x < 9; x++) cp4(db + s2 + 4 * x, st + g2 + x);
        }
        asm volatile("cp.async.commit_group;" ::: "memory");
    }

    // ---- consumer identity: 12 warps = 4(M) x 3(N) ----
    const int wid  = tid >> 5, lane = tid & 31;
    const int g    = lane >> 2, tl = lane & 3;
    const int wm   = wid & 3;          // oc base wm*32
    const int wn   = wid >> 2;         // n  base wn*48
    const int n0   = wn * 48;
    const int rA   = wm * 32 + g;
    float bv[4];
    #pragma unroll
    for (int m = 0; m < 4; m++) bv[m] = bias[k * COUT + rA + m * 8];

    // packed A base: uint4 layout [k][wm][ks][mf][lane], 1024 uint4 per (k,wm)
    const uint4* wpbase = reinterpret_cast<const uint4*>(g_W2)
                          + (size_t)(k * 4 + wm) * 1024 + lane;

    float d[2][6][4];

    for (int s = 0; s < NSTEP; s++) {
        const int qi = s & 3;

        if (qi == 0) {
            #pragma unroll
            for (int mf = 0; mf < 2; mf++)
                #pragma unroll
                for (int nt = 0; nt < 6; nt++)
                    #pragma unroll
                    for (int j = 0; j < 4; j++) d[mf][nt][j] = 0.0f;
        }

        asm volatile("cp.async.wait_group 2;" ::: "memory");   // stage s arrived
        __syncthreads();

        // issue stage s+3 into buffer (s+3)&3 (freed by the sync above)
        if (s + 3 < NSTEP) {
            const int sn = s + 3, tn = sn >> 2, qn = sn & 3;
            const float* st = src + (size_t)(tn * NB) * (CIN * 81) + qn * 32 * 81;
            const uint32_t db = sx_base + qn * (XQ_WORDS * 4);
            #pragma unroll
            for (int x = 0; x < 9; x++) cp4(db + s1 + 4 * x, st + g1 + x);
            if (two) {
                #pragma unroll
                for (int x = 0; x < 9; x++) cp4(db + s2 + 4 * x, st + g2 + x);
            }
        }
        asm volatile("cp.async.commit_group;" ::: "memory");   // possibly empty group

        // ---- MMA on stage qi: 4 k-steps; per kstep: 2 LDG.128 A, 12 LDS B, 12 HMMA ----
        {
            const uint32_t* pb = sX + qi * XQ_WORDS + tl * SXS + g + n0;
            #pragma unroll
            for (int kk2 = 0; kk2 < 4; kk2++) {
                const int ks = qi * 4 + kk2;
                uint4 av0 = wpbase[ks * 64];          // mf0
                uint4 av1 = wpbase[ks * 64 + 32];     // mf1
                uint32_t a0[4] = {av0.x, av0.y, av0.z, av0.w};
                uint32_t a1[4] = {av1.x, av1.y, av1.z, av1.w};

                uint32_t b[6][2];
                #pragma unroll
                for (int nt = 0; nt < 6; nt++) {
                    b[nt][0] = pb[nt * 8];
                    b[nt][1] = pb[4 * SXS + nt * 8];
                }
                #pragma unroll
                for (int nt = 0; nt < 6; nt++) {
                    mma_tf32(d[0][nt], a0, b[nt]);
                    mma_tf32(d[1][nt], a1, b[nt]);
                }
                pb += 8 * SXS;
            }
        }

        // ---- tile boundary: epilogue (direct STG) ----
        if (qi == 3) {
            const int t = s >> 2;
            float* ob = out + ((size_t)(bbase + t * NB) * 9 + k) * 1152;
            #pragma unroll
            for (int mf = 0; mf < 2; mf++) {
                int ra = rA + mf * 16, rb = ra + 8;
                float bva = bv[mf * 2], bvb = bv[mf * 2 + 1];
                #pragma unroll
                for (int nt = 0; nt < 6; nt++) {
                    int n   = n0 + nt * 8 + 2 * tl;
                    int b0q = n / 9,       x0 = n - 9 * b0q;
                    int b1q = (n + 1) / 9, x1 = (n + 1) - 9 * b1q;
                    float* c0 = ob + (size_t)b0q * 10368;
                    float* c1 = ob + (size_t)b1q * 10368;
                    c0[ra * 9 + x0] = d[mf][nt][0] + bva;
                    c1[ra * 9 + x1] = d[mf][nt][1] + bva;
                    c0[rb * 9 + x0] = d[mf][nt][2] + bvb;
                    c1[rb * 9 + x1] = d[mf][nt][3] + bvb;
                }
            }
        }
    }
}

extern "C" void kernel_launch(void* const* d_in, const int* in_sizes, int n_in,
                              void* d_out, int out_size)
{
    const float* in   = (const float*)d_in[0];
    const float* w    = (const float*)d_in[1];
    const float* bias = (const float*)d_in[2];
    float* out        = (float*)d_out;

    int B = in_sizes[0] / (CIN * 81);        // 4096

    prep_w_kernel<<<(W2_WORDS + 255) / 256, 256>>>(w);

    cudaFuncSetAttribute(gather_vertical_r13,
                         cudaFuncAttributeMaxDynamicSharedMemorySize, SMEM_BYTES);

    dim3 grid(KK, B / (NB * TILES));         // (9, 64)
    gather_vertical_r13<<<grid, NTHR, SMEM_BYTES>>>(in, bias, out);
}

// round 14
// speedup vs baseline: 1.3098x; 1.3098x over previous
#include <cuda_runtime.h>
#include <cstdint>

// out[b,k,oc,x] = sum_ci W[k,oc,ci]*in[b,ci,k,x] + bias[k,oc]
// in: [4096,128,9,9]  w: [9,128,128]  bias: [9,128]  out: [4096,9,128,9] (f32)
//
// R14 = R12 (4Mx3N warps, warp tile 32oc x 24n, A packed in g_W2, cp.async X)
// with a deeper ring: 6 quarter-K stages, prologue 5, wait_group 4.

#define KK     9
#define CIN    128
#define COUT   128
#define NB     8
#define TILES  4
#define NTHR   384
#define NBUF   6
#define NSTEP  (NBUF0_UNUSED + NBUF * 0 + 16)    // placeholder guard (see below)
#undef  NSTEP
#define NSTEP  (4 * TILES)      // 16 quarters per CTA (4 quarters per tile)

#define SXS 72                  // stage stride: B-frag banks (8tl+8nt+g... per-LDS distinct) perfect
#define XQ_WORDS (32 * SXS)     // 2304 words per quarter (9216 B)
#define SMEM_BYTES (NBUF * XQ_WORDS * 4)   // 55296 -> 2 CTAs/SM (dynamic)

// packed A-frags: [k][wm(4)][ks(16)][mf(2)][lane(32)][4] tf32 bits
#define W2_WORDS (KK * 4 * 16 * 2 * 32 * 4)   // 147456
__device__ uint32_t g_W2[W2_WORDS];

__device__ __forceinline__ uint32_t f2tf32(float f) {
    uint32_t u;
    asm("cvt.rna.tf32.f32 %0, %1;" : "=r"(u) : "f"(f));
    return u;
}
__device__ __forceinline__ uint32_t smem_u32(const void* p) {
    uint32_t a;
    asm("{ .reg .u64 t; cvta.to.shared.u64 t, %1; cvt.u32.u64 %0, t; }" : "=r"(a) : "l"(p));
    return a;
}
__device__ __forceinline__ void cp4(uint32_t dst, const float* src) {
    asm volatile("cp.async.ca.shared.global [%0], [%1], 4;" :: "r"(dst), "l"(src));
}
__device__ __forceinline__ void mma_tf32(float* d, const uint32_t* a, const uint32_t* b) {
    asm volatile(
        "mma.sync.aligned.m16n8k8.row.col.f32.tf32.tf32.f32 "
        "{%0,%1,%2,%3}, {%4,%5,%6,%7}, {%8,%9}, {%0,%1,%2,%3};"
        : "+f"(d[0]), "+f"(d[1]), "+f"(d[2]), "+f"(d[3])
        : "r"(a[0]), "r"(a[1]), "r"(a[2]), "r"(a[3]), "r"(b[0]), "r"(b[1]));
}

// ---- prep: w[9][128][128] f32 -> g_W2 packed tf32 A-frags ----
__global__ void prep_w_kernel(const float* __restrict__ w) {
    int idx = blockIdx.x * 256 + threadIdx.x;      // 0..147455
    if (idx >= W2_WORDS) return;
    int j    = idx & 3;
    int lane = (idx >> 2) & 31;
    int mf   = (idx >> 7) & 1;
    int ks   = (idx >> 8) & 15;
    int wm   = (idx >> 12) & 3;
    int k    = idx >> 14;
    int g = lane >> 2, tl = lane & 3;
    int oc = wm * 32 + mf * 16 + g + (j & 1) * 8;
    int ci = ks * 8 + tl + ((j >> 1) & 1) * 4;
    g_W2[idx] = f2tf32(w[(k * COUT + oc) * CIN + ci]);
}

__global__ void __launch_bounds__(NTHR, 2)
gather_vertical_r14(const float* __restrict__ in,
                    const float* __restrict__ bias,
                    float* __restrict__ out)
{
    extern __shared__ uint32_t sX[];               // 6 stages [32 ci][72 n]

    const int tid = threadIdx.x;
    const int k   = blockIdx.x;
    const int yid = blockIdx.y;
    const int bbase = yid * TILES * NB;

    // ---- per-thread cp.async offsets (6 words per stage), loop-invariant ----
    const float* src = in + (size_t)bbase * (CIN * 81) + (size_t)k * 9;
    const uint32_t sx_base = smem_u32(sX);
    int goff[6], soff[6];
    #pragma unroll
    for (int j = 0; j < 6; j++) {
        int e  = tid + NTHR * j;      // 0..2303
        int q  = e / 9;               // bl*32 + ci_local
        int x  = e - 9 * q;
        int bl = q >> 5;
        int ci = q & 31;
        goff[j] = (bl * CIN + ci) * 81 + x;
        soff[j] = (ci * SXS + bl * 9 + x) * 4;
    }

    // ---- prologue: stages 0..4 (quarters 0..4 = tile0 q0-3, tile1 q0) ----
    #pragma unroll
    for (int s = 0; s < NBUF - 1; s++) {
        const int tn = s >> 2, qn = s & 3;
        const float* st = src + (size_t)(tn * NB) * (CIN * 81) + qn * 32 * 81;
        const uint32_t db = sx_base + (s % NBUF) * (XQ_WORDS * 4);
        #pragma unroll
        for (int j = 0; j < 6; j++) cp4(db + soff[j], st + goff[j]);
        asm volatile("cp.async.commit_group;" ::: "memory");
    }

    // ---- consumer identity: 12 warps = 4(M) x 3(N) ----
    const int wid  = tid >> 5, lane = tid & 31;
    const int g    = lane >> 2, tl = lane & 3;
    const int wm   = wid & 3;          // oc base wm*32
    const int wn   = wid >> 2;         // n  base wn*24
    const int n0   = wn * 24;
    const int rA   = wm * 32 + g;
    float bv[4];
    #pragma unroll
    for (int m = 0; m < 4; m++) bv[m] = bias[k * COUT + rA + m * 8];

    // packed A base: uint4 layout [k][wm][ks][mf][lane], 1024 uint4 per (k,wm)
    const uint4* wpbase = reinterpret_cast<const uint4*>(g_W2)
                          + (size_t)(k * 4 + wm) * 1024 + lane;

    float d[2][3][4];

    for (int s = 0; s < NSTEP; s++) {
        const int bi = s % NBUF;          // consuming buffer
        const int qi = s & 3;             // quarter within tile

        if (qi == 0) {
            #pragma unroll
            for (int mf = 0; mf < 2; mf++)
                #pragma unroll
                for (int nt = 0; nt < 3; nt++)
                    #pragma unroll
                    for (int j = 0; j < 4; j++) d[mf][nt][j] = 0.0f;
        }

        asm volatile("cp.async.wait_group %0;" :: "n"(NBUF - 2) : "memory"); // stage s arrived
        __syncthreads();

        // issue stage s+NBUF-1 into buffer (s-1)%NBUF (freed by the sync above)
        {
            const int sn = s + NBUF - 1;
            if (sn < NSTEP) {
                const int tn = sn >> 2, qn = sn & 3, bn = sn % NBUF;
                const float* st = src + (size_t)(tn * NB) * (CIN * 81) + qn * 32 * 81;
                const uint32_t db = sx_base + bn * (XQ_WORDS * 4);
                #pragma unroll
                for (int j = 0; j < 6; j++) cp4(db + soff[j], st + goff[j]);
            }
            asm volatile("cp.async.commit_group;" ::: "memory");  // possibly empty group
        }

        // ---- MMA on buffer bi: 4 k-steps; per kstep: 2 LDG.128 A, 6 LDS B, 6 HMMA ----
        {
            const uint32_t* pb = sX + bi * XQ_WORDS + tl * SXS + g + n0;
            #pragma unroll
            for (int kk2 = 0; kk2 < 4; kk2++) {
                const int ks = qi * 4 + kk2;
                uint4 av0 = wpbase[ks * 64];          // mf0
                uint4 av1 = wpbase[ks * 64 + 32];     // mf1
                uint32_t a0[4] = {av0.x, av0.y, av0.z, av0.w};
                uint32_t a1[4] = {av1.x, av1.y, av1.z, av1.w};

                uint32_t b[3][2];
                #pragma unroll
                for (int nt = 0; nt < 3; nt++) {
                    b[nt][0] = pb[nt * 8];
                    b[nt][1] = pb[4 * SXS + nt * 8];
                }
                #pragma unroll
                for (int nt = 0; nt < 3; nt++) {
                    mma_tf32(d[0][nt], a0, b[nt]);
                    mma_tf32(d[1][nt], a1, b[nt]);
                }
                pb += 8 * SXS;
            }
        }

        // ---- tile boundary: epilogue (direct STG) ----
        if (qi == 3) {
            const int t = s >> 2;
            float* ob = out + ((size_t)(bbase + t * NB) * 9 + k) * 1152;
            #pragma unroll
            for (int mf = 0; mf < 2; mf++) {
                int ra = rA + mf * 16, rb = ra + 8;
                float bva = bv[mf * 2], bvb = bv[mf * 2 + 1];
                #pragma unroll
                for (int nt = 0; nt < 3; nt++) {
                    int n   = n0 + nt * 8 + 2 * tl;
                    int b0q = n / 9,       x0 = n - 9 * b0q;
                    int b1q = (n + 1) / 9, x1 = (n + 1) - 9 * b1q;
                    float* c0 = ob + (size_t)b0q * 10368;
                    float* c1 = ob + (size_t)b1q * 10368;
                    c0[ra * 9 + x0] = d[mf][nt][0] + bva;
                    c1[ra * 9 + x1] = d[mf][nt][1] + bva;
                    c0[rb * 9 + x0] = d[mf][nt][2] + bvb;
                    c1[rb * 9 + x1] = d[mf][nt][3] + bvb;
                }
            }
        }
    }
}

extern "C" void kernel_launch(void* const* d_in, const int* in_sizes, int n_in,
                              void* d_out, int out_size)
{
    const float* in   = (const float*)d_in[0];
    const float* w    = (const float*)d_in[1];
    const float* bias = (const float*)d_in[2];
    float* out        = (float*)d_out;

    int B = in_sizes[0] / (CIN * 81);        // 4096

    prep_w_kernel<<<(W2_WORDS + 255) / 256, 256>>>(w);

    cudaFuncSetAttribute(gather_vertical_r14,
                         cudaFuncAttributeMaxDynamicSharedMemorySize, SMEM_BYTES);

    dim3 grid(KK, B / (NB * TILES));         // (9, 128)
    gather_vertical_r14<<<grid, NTHR, SMEM_BYTES>>>(in, bias, out);
}